// round 11
// baseline (speedup 1.0000x reference)
#include <cuda_runtime.h>
#include <cuda_fp16.h>
#include <cstdint>

// ChunkStickyRouter on GB300 (sm_103a) — fp16 mma.sync GEMM1 (in-kernel x cvt),
// fused logits+scan (smem scan), wide one-hot fill.
// B=8, S=4096, D=2048, H=1024, E=8, CHUNK=128, TAU=0.7

#define B_  8
#define S_  4096
#define D_  2048
#define H_  1024
#define E_  8
#define CHUNK_ 128
#define NCHUNK_ 256
#define TAU_ 0.7f

// GEMM1 tiling
#define BM_ 128
#define BN_ 128
#define BK_ 32
#define NKC_ (D_ / BK_)        // 64
#define NTHR_ 256
#define ROWB_ 80               // smem row stride (bytes): conflict-free LDSM
#define ATILE_ (128 * ROWB_)           // 10240 B (fp16)
#define BTILE_ (128 * ROWB_)           // 10240 B (fp16)
#define STAGE_SZ_ (ATILE_ + BTILE_)    // 20480
#define SM_B1_   (3 * STAGE_SZ_)       // 61440
#define SM_PART_ (SM_B1_ + 512)
#define SMEM_TOTAL_ (SM_PART_ + 1024)  // 62976  -> 2 CTAs/SM

__device__ __half g_w1t[(size_t)H_ * D_];         // W1^T as fp16, [n][k]
__device__ float  g_hsum[NCHUNK_ * H_];
__device__ int    g_eidx[NCHUNK_];

// ---------------- PTX helpers ----------------
__device__ __forceinline__ uint32_t smem_to_u32(const void* p) {
    uint32_t a;
    asm("{ .reg .u64 t; cvta.to.shared.u64 t, %1; cvt.u32.u64 %0, t; }" : "=r"(a) : "l"(p));
    return a;
}
// pack two fp32 -> f16x2 (lo = x, hi = y), result as u32
__device__ __forceinline__ uint32_t pack_half2(float x, float y) {
    uint32_t u;
    asm("cvt.rn.f16x2.f32 %0, %1, %2;" : "=r"(u) : "f"(y), "f"(x));
    return u;
}
#define CP_ASYNC16(dst, src) \
    asm volatile("cp.async.cg.shared.global [%0], [%1], 16;" :: "r"(dst), "l"(src))
#define CP_COMMIT() asm volatile("cp.async.commit_group;" ::: "memory")
#define CP_WAIT1()  asm volatile("cp.async.wait_group 1;" ::: "memory")

#define LDSM4(r, a) \
    asm volatile("ldmatrix.sync.aligned.m8n8.x4.shared.b16 {%0,%1,%2,%3}, [%4];" \
        : "=r"((r)[0]), "=r"((r)[1]), "=r"((r)[2]), "=r"((r)[3]) : "r"(a))
#define LDSM2(r, a) \
    asm volatile("ldmatrix.sync.aligned.m8n8.x2.shared.b16 {%0,%1}, [%2];" \
        : "=r"((r)[0]), "=r"((r)[1]) : "r"(a))

#define MMA_F32(d, a, b) \
    asm volatile("mma.sync.aligned.m16n8k16.row.col.f32.f16.f16.f32 " \
        "{%0,%1,%2,%3}, {%4,%5,%6,%7}, {%8,%9}, {%0,%1,%2,%3};" \
        : "+f"((d)[0]), "+f"((d)[1]), "+f"((d)[2]), "+f"((d)[3]) \
        : "r"((a)[0]), "r"((a)[1]), "r"((a)[2]), "r"((a)[3]), "r"((b)[0]), "r"((b)[1]))

#define STS64(addr, v0, v1) \
    asm volatile("st.shared.v2.b32 [%0], {%1, %2};" :: "r"(addr), "r"(v0), "r"(v1))

// ---------------- prepass: W1 [k][n] fp32 -> W1^T [n][k] fp16 ----------------
__global__ void cvt_w1(const float* __restrict__ W1) {
    __shared__ float t[32][33];
    int n0 = blockIdx.x * 32, k0 = blockIdx.y * 32;
    int tx = threadIdx.x, ty = threadIdx.y;
    #pragma unroll
    for (int i = 0; i < 4; i++)
        t[ty + i * 8][tx] = W1[(size_t)(k0 + ty + i * 8) * H_ + n0 + tx];
    __syncthreads();
    #pragma unroll
    for (int i = 0; i < 4; i++) {
        int n = ty + i * 8, k = tx;
        g_w1t[(size_t)(n0 + n) * D_ + k0 + k] = __float2half_rn(t[k][n]);
    }
}

// ---------------- GEMM1: relu(x@W1+b1) with fused chunk column-sum ----------------
__global__ __launch_bounds__(NTHR_, 2)
void gemm1_mma(const float* __restrict__ x, const float* __restrict__ b1) {
    extern __shared__ __align__(1024) char smem[];
    const uint32_t sb = smem_to_u32(smem);
    const int tid = threadIdx.x;
    const int lane = tid & 31, wid = tid >> 5;      // 8 warps
    const int wm = wid & 1, wn = wid >> 1;          // 2(m) x 4(n), warp tile 64x32
    const int n0 = blockIdx.x * BN_;
    const int chunk = blockIdx.y;
    const int m0 = chunk * BM_;

    if (tid < BN_) ((float*)(smem + SM_B1_))[tid] = b1[n0 + tid];

    // ---- A (x fp32, LDG prefetch): thread covers 4 float4 chunks ----
    const int a_row0 = tid >> 3;            // +32*j
    const int a_k4   = tid & 7;
    const float* srcA0 = x + (size_t)(m0 + a_row0) * D_ + a_k4 * 4;
    const uint32_t dstA0 = sb + a_row0 * ROWB_ + a_k4 * 8;   // fp16: 8B per float4

    // ---- B (w1t fp16, cp.async): 2 chunks of 16B per thread ----
    const char* srcB[2]; uint32_t dstB[2];
    #pragma unroll
    for (int j = 0; j < 2; j++) {
        int q = tid + j * NTHR_;               // 0..511
        int row = q >> 2, k16 = q & 3;
        srcB[j] = (const char*)(g_w1t + (size_t)(n0 + row) * D_ + k16 * 8);
        dstB[j] = sb + ATILE_ + row * ROWB_ + k16 * 16;
    }

    const uint32_t a_off = (uint32_t)((wm * 64 + (lane & 15)) * ROWB_ + (lane >> 4) * 16);
    const uint32_t b_off = (uint32_t)(ATILE_ + (wn * 32 + (lane & 7)) * ROWB_ + ((lane >> 3) & 1) * 16);

    float acc[4][4][4];
    #pragma unroll
    for (int a = 0; a < 4; a++)
        #pragma unroll
        for (int b = 0; b < 4; b++)
            #pragma unroll
            for (int c = 0; c < 4; c++) acc[a][b][c] = 0.f;

    float4 areg[4];

    // ---- prologue ----
    #pragma unroll
    for (int j = 0; j < 4; j++)
        areg[j] = *(const float4*)(srcA0 + (size_t)(32 * j) * D_);
    #pragma unroll
    for (int j = 0; j < 4; j++) {
        uint32_t h0 = pack_half2(areg[j].x, areg[j].y);
        uint32_t h1 = pack_half2(areg[j].z, areg[j].w);
        STS64(dstA0 + j * (32 * ROWB_), h0, h1);
    }
    #pragma unroll
    for (int j = 0; j < 4; j++)
        areg[j] = *(const float4*)(srcA0 + (size_t)(32 * j) * D_ + BK_);
    #pragma unroll
    for (int s = 0; s < 2; s++) {
        uint32_t sbase = s * STAGE_SZ_;
        #pragma unroll
        for (int j = 0; j < 2; j++)
            CP_ASYNC16(dstB[j] + sbase, srcB[j] + s * 64);
        CP_COMMIT();
    }

    int buf = 0;
    for (int ck = 0; ck < NKC_; ck++) {
        CP_WAIT1();
        __syncthreads();

        // stage A(ck+1) regs -> smem buf (ck+1)%3 ; prefetch A(ck+2); B(ck+2) cp.async
        if (ck + 1 < NKC_) {
            int nb1 = buf + 1; if (nb1 >= 3) nb1 -= 3;
            uint32_t ab = dstA0 + nb1 * STAGE_SZ_;
            #pragma unroll
            for (int j = 0; j < 4; j++) {
                uint32_t h0 = pack_half2(areg[j].x, areg[j].y);
                uint32_t h1 = pack_half2(areg[j].z, areg[j].w);
                STS64(ab + j * (32 * ROWB_), h0, h1);
            }
        }
        if (ck + 2 < NKC_) {
            #pragma unroll
            for (int j = 0; j < 4; j++)
                areg[j] = *(const float4*)(srcA0 + (size_t)(32 * j) * D_ + (size_t)(ck + 2) * BK_);
            int nb2 = buf + 2; if (nb2 >= 3) nb2 -= 3;
            uint32_t sbase = nb2 * STAGE_SZ_;
            #pragma unroll
            for (int j = 0; j < 2; j++)
                CP_ASYNC16(dstB[j] + sbase, srcB[j] + (size_t)(ck + 2) * 64);
        }
        CP_COMMIT();

        const uint32_t bufbase = sb + buf * STAGE_SZ_;
        #pragma unroll
        for (int kk = 0; kk < 2; kk++) {
            uint32_t ah[4][4], bh[4][2];
            uint32_t ab = bufbase + a_off + kk * 32;
            uint32_t bb = bufbase + b_off + kk * 32;
            #pragma unroll
            for (int mt = 0; mt < 4; mt++) LDSM4(ah[mt], ab + mt * (16 * ROWB_));
            #pragma unroll
            for (int nt = 0; nt < 4; nt++) LDSM2(bh[nt], bb + nt * (8 * ROWB_));
            #pragma unroll
            for (int mt = 0; mt < 4; mt++)
                #pragma unroll
                for (int nt = 0; nt < 4; nt++)
                    MMA_F32(acc[mt][nt], ah[mt], bh[nt]);
        }
        buf++; if (buf >= 3) buf = 0;
    }

    // ---- epilogue: relu(acc + b1), chunk column-sums ----
    const float* sb1f = (const float*)(smem + SM_B1_);
    float csum[4][2];
    #pragma unroll
    for (int nt = 0; nt < 4; nt++) { csum[nt][0] = 0.f; csum[nt][1] = 0.f; }
    #pragma unroll
    for (int nt = 0; nt < 4; nt++) {
        int col = wn * 32 + nt * 8 + (lane & 3) * 2;
        float bv0 = sb1f[col], bv1 = sb1f[col + 1];
        #pragma unroll
        for (int mt = 0; mt < 4; mt++) {
            csum[nt][0] += fmaxf(acc[mt][nt][0] + bv0, 0.f) + fmaxf(acc[mt][nt][2] + bv0, 0.f);
            csum[nt][1] += fmaxf(acc[mt][nt][1] + bv1, 0.f) + fmaxf(acc[mt][nt][3] + bv1, 0.f);
        }
    }
    #pragma unroll
    for (int nt = 0; nt < 4; nt++)
        #pragma unroll
        for (int r = 0; r < 2; r++) {
            csum[nt][r] += __shfl_xor_sync(0xffffffffu, csum[nt][r], 4);
            csum[nt][r] += __shfl_xor_sync(0xffffffffu, csum[nt][r], 8);
            csum[nt][r] += __shfl_xor_sync(0xffffffffu, csum[nt][r], 16);
        }
    float* part = (float*)(smem + SM_PART_);    // [2][128]
    __syncthreads();
    if (lane < 4) {
        #pragma unroll
        for (int nt = 0; nt < 4; nt++) {
            int col = wn * 32 + nt * 8 + lane * 2;
            part[wm * BN_ + col] = csum[nt][0];
            part[wm * BN_ + col + 1] = csum[nt][1];
        }
    }
    __syncthreads();
    if (tid < BN_)
        g_hsum[(size_t)chunk * H_ + n0 + tid] = part[tid] + part[BN_ + tid];
}

// ---------------- logits + hysteresis scan (smem), one block per batch ----------------
__global__ __launch_bounds__(256)
void logits_scan(const float* __restrict__ W2, const float* __restrict__ b2,
                 float* __restrict__ out, int out_size) {
    __shared__ float clog[32][E_];
    __shared__ int   sidx[32];
    const int b = blockIdx.x;
    const int tid = threadIdx.x;
    const int lane = tid & 31, w = tid >> 5;   // 8 warps

    // 1) chunk logits: warp w handles chunks w*4 .. w*4+3
    #pragma unroll
    for (int i = 0; i < 4; i++) {
        int c = w * 4 + i;
        const float* hs = g_hsum + (size_t)(b * 32 + c) * H_;
        float acc[E_];
        #pragma unroll
        for (int e = 0; e < E_; e++) acc[e] = 0.f;
        for (int j = lane; j < H_; j += 32) {
            float h = hs[j];
            float4 w0 = *(const float4*)(W2 + (size_t)j * E_);
            float4 w1 = *(const float4*)(W2 + (size_t)j * E_ + 4);
            acc[0] += h * w0.x; acc[1] += h * w0.y; acc[2] += h * w0.z; acc[3] += h * w0.w;
            acc[4] += h * w1.x; acc[5] += h * w1.y; acc[6] += h * w1.z; acc[7] += h * w1.w;
        }
        #pragma unroll
        for (int off = 16; off; off >>= 1)
            #pragma unroll
            for (int e = 0; e < E_; e++)
                acc[e] += __shfl_down_sync(0xffffffffu, acc[e], off);
        if (lane == 0) {
            #pragma unroll
            for (int e = 0; e < E_; e++)
                clog[c][e] = acc[e] * (1.0f / (float)CHUNK_) + b2[e];
        }
    }
    __syncthreads();

    // 2) hysteresis scan from smem
    if (tid == 0) {
        int prev = 0;
        {
            float best = clog[0][0];
            #pragma unroll
            for (int e = 1; e < E_; e++)
                if (clog[0][e] > best) { best = clog[0][e]; prev = e; }
        }
        sidx[0] = prev;
        for (int c = 1; c < 32; c++) {
            int ce = 0; float best = clog[c][0];
            #pragma unroll
            for (int e = 1; e < E_; e++)
                if (clog[c][e] > best) { best = clog[c][e]; ce = e; }
            if (clog[c][ce] - clog[c][prev] > TAU_) prev = ce;
            sidx[c] = prev;
        }
    }
    __syncthreads();

    if (tid < 32) {
        g_eidx[b * 32 + tid] = sidx[tid];
        if (out_size >= B_ * S_ * E_ + NCHUNK_)
            out[B_ * S_ * E_ + b * 32 + tid] = (float)sidx[tid];
    }
}

// ---------------- one-hot fill (wide: 256 blocks) ----------------
__global__ void fill_routing(float* __restrict__ out) {
    int q = blockIdx.x * blockDim.x + threadIdx.x;
    int token = q >> 1;
    int e0 = (q & 1) * 4;
    int idx = g_eidx[token >> 7];
    float4 v;
    v.x = (e0 + 0 == idx) ? 1.0f : 0.0f;
    v.y = (e0 + 1 == idx) ? 1.0f : 0.0f;
    v.z = (e0 + 2 == idx) ? 1.0f : 0.0f;
    v.w = (e0 + 3 == idx) ? 1.0f : 0.0f;
    ((float4*)out)[q] = v;
}

extern "C" void kernel_launch(void* const* d_in, const int* in_sizes, int n_in,
                              void* d_out, int out_size) {
    const float* x  = (const float*)d_in[0];
    const float* W1 = (const float*)d_in[1];
    const float* b1 = (const float*)d_in[2];
    const float* W2 = (const float*)d_in[3];
    const float* b2 = (const float*)d_in[4];
    float* out = (float*)d_out;

    cudaFuncSetAttribute(gemm1_mma, cudaFuncAttributeMaxDynamicSharedMemorySize, SMEM_TOTAL_);

    cvt_w1<<<dim3(H_ / 32, D_ / 32), dim3(32, 8)>>>(W1);
    gemm1_mma<<<dim3(H_ / BN_, NCHUNK_), NTHR_, SMEM_TOTAL_>>>(x, b1);
    logits_scan<<<B_, 256>>>(W2, b2, out, out_size);
    fill_routing<<<(B_ * S_ * E_ / 4) / 256, 256>>>(out);
}

// round 12
// speedup vs baseline: 1.0835x; 1.0835x over previous
#include <cuda_runtime.h>
#include <cuda_fp16.h>
#include <cstdint>

// ChunkStickyRouter on GB300 (sm_103a) — fp16 mma.sync GEMM1 (in-kernel x cvt),
// wide gemm2, smem-staged hysteresis scan, wide one-hot fill.
// B=8, S=4096, D=2048, H=1024, E=8, CHUNK=128, TAU=0.7

#define B_  8
#define S_  4096
#define D_  2048
#define H_  1024
#define E_  8
#define CHUNK_ 128
#define NCHUNK_ 256
#define TAU_ 0.7f

// GEMM1 tiling
#define BM_ 128
#define BN_ 128
#define BK_ 32
#define NKC_ (D_ / BK_)        // 64
#define NTHR_ 256
#define ROWB_ 80               // smem row stride (bytes): conflict-free LDSM
#define ATILE_ (128 * ROWB_)           // 10240 B (fp16)
#define BTILE_ (128 * ROWB_)           // 10240 B (fp16)
#define STAGE_SZ_ (ATILE_ + BTILE_)    // 20480
#define SM_B1_   (3 * STAGE_SZ_)       // 61440
#define SM_PART_ (SM_B1_ + 512)
#define SMEM_TOTAL_ (SM_PART_ + 1024)  // 62976  -> 2 CTAs/SM

__device__ __half g_w1t[(size_t)H_ * D_];         // W1^T as fp16, [n][k]
__device__ float  g_hsum[NCHUNK_ * H_];
__device__ float  g_clogits[NCHUNK_ * E_];
__device__ int    g_eidx[NCHUNK_];

// ---------------- PTX helpers ----------------
__device__ __forceinline__ uint32_t smem_to_u32(const void* p) {
    uint32_t a;
    asm("{ .reg .u64 t; cvta.to.shared.u64 t, %1; cvt.u32.u64 %0, t; }" : "=r"(a) : "l"(p));
    return a;
}
// pack two fp32 -> f16x2 (lo = x, hi = y), result as u32
__device__ __forceinline__ uint32_t pack_half2(float x, float y) {
    uint32_t u;
    asm("cvt.rn.f16x2.f32 %0, %1, %2;" : "=r"(u) : "f"(y), "f"(x));
    return u;
}
#define CP_ASYNC16(dst, src) \
    asm volatile("cp.async.cg.shared.global [%0], [%1], 16;" :: "r"(dst), "l"(src))
#define CP_COMMIT() asm volatile("cp.async.commit_group;" ::: "memory")
#define CP_WAIT1()  asm volatile("cp.async.wait_group 1;" ::: "memory")

#define LDSM4(r, a) \
    asm volatile("ldmatrix.sync.aligned.m8n8.x4.shared.b16 {%0,%1,%2,%3}, [%4];" \
        : "=r"((r)[0]), "=r"((r)[1]), "=r"((r)[2]), "=r"((r)[3]) : "r"(a))
#define LDSM2(r, a) \
    asm volatile("ldmatrix.sync.aligned.m8n8.x2.shared.b16 {%0,%1}, [%2];" \
        : "=r"((r)[0]), "=r"((r)[1]) : "r"(a))

#define MMA_F32(d, a, b) \
    asm volatile("mma.sync.aligned.m16n8k16.row.col.f32.f16.f16.f32 " \
        "{%0,%1,%2,%3}, {%4,%5,%6,%7}, {%8,%9}, {%0,%1,%2,%3};" \
        : "+f"((d)[0]), "+f"((d)[1]), "+f"((d)[2]), "+f"((d)[3]) \
        : "r"((a)[0]), "r"((a)[1]), "r"((a)[2]), "r"((a)[3]), "r"((b)[0]), "r"((b)[1]))

#define STS64(addr, v0, v1) \
    asm volatile("st.shared.v2.b32 [%0], {%1, %2};" :: "r"(addr), "r"(v0), "r"(v1))

// ---------------- prepass: W1 [k][n] fp32 -> W1^T [n][k] fp16 ----------------
__global__ void cvt_w1(const float* __restrict__ W1) {
    __shared__ float t[32][33];
    int n0 = blockIdx.x * 32, k0 = blockIdx.y * 32;
    int tx = threadIdx.x, ty = threadIdx.y;
    #pragma unroll
    for (int i = 0; i < 4; i++)
        t[ty + i * 8][tx] = W1[(size_t)(k0 + ty + i * 8) * H_ + n0 + tx];
    __syncthreads();
    #pragma unroll
    for (int i = 0; i < 4; i++) {
        int n = ty + i * 8, k = tx;
        g_w1t[(size_t)(n0 + n) * D_ + k0 + k] = __float2half_rn(t[k][n]);
    }
}

// ---------------- GEMM1: relu(x@W1+b1) with fused chunk column-sum ----------------
__global__ __launch_bounds__(NTHR_, 2)
void gemm1_mma(const float* __restrict__ x, const float* __restrict__ b1) {
    extern __shared__ __align__(1024) char smem[];
    const uint32_t sb = smem_to_u32(smem);
    const int tid = threadIdx.x;
    const int lane = tid & 31, wid = tid >> 5;      // 8 warps
    const int wm = wid & 1, wn = wid >> 1;          // 2(m) x 4(n), warp tile 64x32
    const int n0 = blockIdx.x * BN_;
    const int chunk = blockIdx.y;
    const int m0 = chunk * BM_;

    if (tid < BN_) ((float*)(smem + SM_B1_))[tid] = b1[n0 + tid];

    // ---- A (x fp32, LDG prefetch): thread covers 4 float4 chunks ----
    const int a_row0 = tid >> 3;            // +32*j
    const int a_k4   = tid & 7;
    const float* srcA0 = x + (size_t)(m0 + a_row0) * D_ + a_k4 * 4;
    const uint32_t dstA0 = sb + a_row0 * ROWB_ + a_k4 * 8;   // fp16: 8B per float4

    // ---- B (w1t fp16, cp.async): 2 chunks of 16B per thread ----
    const char* srcB[2]; uint32_t dstB[2];
    #pragma unroll
    for (int j = 0; j < 2; j++) {
        int q = tid + j * NTHR_;               // 0..511
        int row = q >> 2, k16 = q & 3;
        srcB[j] = (const char*)(g_w1t + (size_t)(n0 + row) * D_ + k16 * 8);
        dstB[j] = sb + ATILE_ + row * ROWB_ + k16 * 16;
    }

    const uint32_t a_off = (uint32_t)((wm * 64 + (lane & 15)) * ROWB_ + (lane >> 4) * 16);
    const uint32_t b_off = (uint32_t)(ATILE_ + (wn * 32 + (lane & 7)) * ROWB_ + ((lane >> 3) & 1) * 16);

    float acc[4][4][4];
    #pragma unroll
    for (int a = 0; a < 4; a++)
        #pragma unroll
        for (int b = 0; b < 4; b++)
            #pragma unroll
            for (int c = 0; c < 4; c++) acc[a][b][c] = 0.f;

    float4 areg[4];

    // ---- prologue ----
    #pragma unroll
    for (int j = 0; j < 4; j++)
        areg[j] = *(const float4*)(srcA0 + (size_t)(32 * j) * D_);
    #pragma unroll
    for (int j = 0; j < 4; j++) {
        uint32_t h0 = pack_half2(areg[j].x, areg[j].y);
        uint32_t h1 = pack_half2(areg[j].z, areg[j].w);
        STS64(dstA0 + j * (32 * ROWB_), h0, h1);
    }
    #pragma unroll
    for (int j = 0; j < 4; j++)
        areg[j] = *(const float4*)(srcA0 + (size_t)(32 * j) * D_ + BK_);
    #pragma unroll
    for (int s = 0; s < 2; s++) {
        uint32_t sbase = s * STAGE_SZ_;
        #pragma unroll
        for (int j = 0; j < 2; j++)
            CP_ASYNC16(dstB[j] + sbase, srcB[j] + s * 64);
        CP_COMMIT();
    }

    int buf = 0;
    for (int ck = 0; ck < NKC_; ck++) {
        CP_WAIT1();
        __syncthreads();

        // stage A(ck+1) regs -> smem buf (ck+1)%3 ; prefetch A(ck+2); B(ck+2) cp.async
        if (ck + 1 < NKC_) {
            int nb1 = buf + 1; if (nb1 >= 3) nb1 -= 3;
            uint32_t ab = dstA0 + nb1 * STAGE_SZ_;
            #pragma unroll
            for (int j = 0; j < 4; j++) {
                uint32_t h0 = pack_half2(areg[j].x, areg[j].y);
                uint32_t h1 = pack_half2(areg[j].z, areg[j].w);
                STS64(ab + j * (32 * ROWB_), h0, h1);
            }
        }
        if (ck + 2 < NKC_) {
            #pragma unroll
            for (int j = 0; j < 4; j++)
                areg[j] = *(const float4*)(srcA0 + (size_t)(32 * j) * D_ + (size_t)(ck + 2) * BK_);
            int nb2 = buf + 2; if (nb2 >= 3) nb2 -= 3;
            uint32_t sbase = nb2 * STAGE_SZ_;
            #pragma unroll
            for (int j = 0; j < 2; j++)
                CP_ASYNC16(dstB[j] + sbase, srcB[j] + (size_t)(ck + 2) * 64);
        }
        CP_COMMIT();

        const uint32_t bufbase = sb + buf * STAGE_SZ_;
        #pragma unroll
        for (int kk = 0; kk < 2; kk++) {
            uint32_t ah[4][4], bh[4][2];
            uint32_t ab = bufbase + a_off + kk * 32;
            uint32_t bb = bufbase + b_off + kk * 32;
            #pragma unroll
            for (int mt = 0; mt < 4; mt++) LDSM4(ah[mt], ab + mt * (16 * ROWB_));
            #pragma unroll
            for (int nt = 0; nt < 4; nt++) LDSM2(bh[nt], bb + nt * (8 * ROWB_));
            #pragma unroll
            for (int mt = 0; mt < 4; mt++)
                #pragma unroll
                for (int nt = 0; nt < 4; nt++)
                    MMA_F32(acc[mt][nt], ah[mt], bh[nt]);
        }
        buf++; if (buf >= 3) buf = 0;
    }

    // ---- epilogue: relu(acc + b1), chunk column-sums ----
    const float* sb1f = (const float*)(smem + SM_B1_);
    float csum[4][2];
    #pragma unroll
    for (int nt = 0; nt < 4; nt++) { csum[nt][0] = 0.f; csum[nt][1] = 0.f; }
    #pragma unroll
    for (int nt = 0; nt < 4; nt++) {
        int col = wn * 32 + nt * 8 + (lane & 3) * 2;
        float bv0 = sb1f[col], bv1 = sb1f[col + 1];
        #pragma unroll
        for (int mt = 0; mt < 4; mt++) {
            csum[nt][0] += fmaxf(acc[mt][nt][0] + bv0, 0.f) + fmaxf(acc[mt][nt][2] + bv0, 0.f);
            csum[nt][1] += fmaxf(acc[mt][nt][1] + bv1, 0.f) + fmaxf(acc[mt][nt][3] + bv1, 0.f);
        }
    }
    #pragma unroll
    for (int nt = 0; nt < 4; nt++)
        #pragma unroll
        for (int r = 0; r < 2; r++) {
            csum[nt][r] += __shfl_xor_sync(0xffffffffu, csum[nt][r], 4);
            csum[nt][r] += __shfl_xor_sync(0xffffffffu, csum[nt][r], 8);
            csum[nt][r] += __shfl_xor_sync(0xffffffffu, csum[nt][r], 16);
        }
    float* part = (float*)(smem + SM_PART_);    // [2][128]
    __syncthreads();
    if (lane < 4) {
        #pragma unroll
        for (int nt = 0; nt < 4; nt++) {
            int col = wn * 32 + nt * 8 + lane * 2;
            part[wm * BN_ + col] = csum[nt][0];
            part[wm * BN_ + col + 1] = csum[nt][1];
        }
    }
    __syncthreads();
    if (tid < BN_)
        g_hsum[(size_t)chunk * H_ + n0 + tid] = part[tid] + part[BN_ + tid];
}

// ---------------- GEMM2 (wide: 256 blocks) ----------------
__global__ void gemm2_logits(const float* __restrict__ W2,
                             const float* __restrict__ b2) {
    const int bc = blockIdx.x;
    const int tid = threadIdx.x;
    const float* hs = g_hsum + (size_t)bc * H_;

    float acc[E_];
    #pragma unroll
    for (int e = 0; e < E_; e++) acc[e] = 0.f;

    for (int j = tid; j < H_; j += 128) {
        float h = hs[j];
        float4 w0 = *(const float4*)(W2 + (size_t)j * E_);
        float4 w1 = *(const float4*)(W2 + (size_t)j * E_ + 4);
        acc[0] += h * w0.x; acc[1] += h * w0.y; acc[2] += h * w0.z; acc[3] += h * w0.w;
        acc[4] += h * w1.x; acc[5] += h * w1.y; acc[6] += h * w1.z; acc[7] += h * w1.w;
    }
    #pragma unroll
    for (int off = 16; off; off >>= 1)
        #pragma unroll
        for (int e = 0; e < E_; e++)
            acc[e] += __shfl_down_sync(0xffffffffu, acc[e], off);

    __shared__ float sred[4][E_];
    if ((tid & 31) == 0) {
        #pragma unroll
        for (int e = 0; e < E_; e++) sred[tid >> 5][e] = acc[e];
    }
    __syncthreads();
    if (tid < E_) {
        float s = sred[0][tid] + sred[1][tid] + sred[2][tid] + sred[3][tid];
        g_clogits[bc * E_ + tid] = s * (1.0f / (float)CHUNK_) + b2[tid];
    }
}

// ---------------- hysteresis scan: coalesced smem stage, then scan ----------------
__global__ __launch_bounds__(256)
void hysteresis_scan(float* __restrict__ out, int out_size) {
    __shared__ float clog[NCHUNK_ * E_];     // 8 KB
    __shared__ int   sidx[NCHUNK_];
    const int tid = threadIdx.x;

    // coalesced load of all chunk logits (2048 floats, 256 threads x 8)
    #pragma unroll
    for (int j = 0; j < 8; j++)
        clog[tid + j * 256] = g_clogits[tid + j * 256];
    __syncthreads();

    if (tid < B_) {
        const float* cl = clog + tid * 32 * E_;
        int prev = 0;
        {
            float best = cl[0];
            #pragma unroll
            for (int e = 1; e < E_; e++)
                if (cl[e] > best) { best = cl[e]; prev = e; }
        }
        sidx[tid * 32] = prev;
        for (int c = 1; c < 32; c++) {
            const float* l = cl + c * E_;
            int ce = 0; float best = l[0];
            #pragma unroll
            for (int e = 1; e < E_; e++)
                if (l[e] > best) { best = l[e]; ce = e; }
            if (l[ce] - l[prev] > TAU_) prev = ce;
            sidx[tid * 32 + c] = prev;
        }
    }
    __syncthreads();

    if (tid < NCHUNK_) {
        g_eidx[tid] = sidx[tid];
        if (out_size >= B_ * S_ * E_ + NCHUNK_)
            out[B_ * S_ * E_ + tid] = (float)sidx[tid];
    }
}

// ---------------- one-hot fill (wide: 256 blocks) ----------------
__global__ void fill_routing(float* __restrict__ out) {
    int q = blockIdx.x * blockDim.x + threadIdx.x;
    int token = q >> 1;
    int e0 = (q & 1) * 4;
    int idx = g_eidx[token >> 7];
    float4 v;
    v.x = (e0 + 0 == idx) ? 1.0f : 0.0f;
    v.y = (e0 + 1 == idx) ? 1.0f : 0.0f;
    v.z = (e0 + 2 == idx) ? 1.0f : 0.0f;
    v.w = (e0 + 3 == idx) ? 1.0f : 0.0f;
    ((float4*)out)[q] = v;
}

extern "C" void kernel_launch(void* const* d_in, const int* in_sizes, int n_in,
                              void* d_out, int out_size) {
    const float* x  = (const float*)d_in[0];
    const float* W1 = (const float*)d_in[1];
    const float* b1 = (const float*)d_in[2];
    const float* W2 = (const float*)d_in[3];
    const float* b2 = (const float*)d_in[4];
    float* out = (float*)d_out;

    cudaFuncSetAttribute(gemm1_mma, cudaFuncAttributeMaxDynamicSharedMemorySize, SMEM_TOTAL_);

    cvt_w1<<<dim3(H_ / 32, D_ / 32), dim3(32, 8)>>>(W1);
    gemm1_mma<<<dim3(H_ / BN_, NCHUNK_), NTHR_, SMEM_TOTAL_>>>(x, b1);
    gemm2_logits<<<NCHUNK_, 128>>>(W2, b2);
    hysteresis_scan<<<1, 256>>>(out, out_size);
    fill_routing<<<(B_ * S_ * E_ / 4) / 256, 256>>>(out);
}

// round 13
// speedup vs baseline: 1.0987x; 1.0140x over previous
#include <cuda_runtime.h>
#include <cuda_fp16.h>
#include <cstdint>

// ChunkStickyRouter on GB300 (sm_103a) — fp16 mma.sync GEMM1 with fused
// x-conversion, fused last-CTA chunk-logits, and per-chunk scan+one-hot fill.
// B=8, S=4096, D=2048, H=1024, E=8, CHUNK=128, TAU=0.7

#define B_  8
#define S_  4096
#define D_  2048
#define H_  1024
#define E_  8
#define CHUNK_ 128
#define NCHUNK_ 256
#define TAU_ 0.7f

// GEMM1 tiling
#define BM_ 128
#define BN_ 128
#define BK_ 32
#define NKC_ (D_ / BK_)        // 64
#define NTHR_ 256
#define ROWB_ 80               // smem row stride (bytes): conflict-free LDSM
#define ATILE_ (128 * ROWB_)           // 10240 B (fp16)
#define BTILE_ (128 * ROWB_)           // 10240 B (fp16)
#define STAGE_SZ_ (ATILE_ + BTILE_)    // 20480
#define SM_B1_   (3 * STAGE_SZ_)       // 61440
#define SM_PART_ (SM_B1_ + 512)
#define SMEM_TOTAL_ (SM_PART_ + 1024)  // 62976  -> 2 CTAs/SM

__device__ __half g_w1t[(size_t)H_ * D_];         // W1^T as fp16, [n][k]
__device__ float  g_hsum[NCHUNK_ * H_];
__device__ float  g_clogits[NCHUNK_ * E_];
__device__ int    g_cnt[NCHUNK_];                 // per-chunk completion counters

// ---------------- PTX helpers ----------------
__device__ __forceinline__ uint32_t smem_to_u32(const void* p) {
    uint32_t a;
    asm("{ .reg .u64 t; cvta.to.shared.u64 t, %1; cvt.u32.u64 %0, t; }" : "=r"(a) : "l"(p));
    return a;
}
// pack two fp32 -> f16x2 (lo = x, hi = y), result as u32
__device__ __forceinline__ uint32_t pack_half2(float x, float y) {
    uint32_t u;
    asm("cvt.rn.f16x2.f32 %0, %1, %2;" : "=r"(u) : "f"(y), "f"(x));
    return u;
}
#define CP_ASYNC16(dst, src) \
    asm volatile("cp.async.cg.shared.global [%0], [%1], 16;" :: "r"(dst), "l"(src))
#define CP_COMMIT() asm volatile("cp.async.commit_group;" ::: "memory")
#define CP_WAIT1()  asm volatile("cp.async.wait_group 1;" ::: "memory")

#define LDSM4(r, a) \
    asm volatile("ldmatrix.sync.aligned.m8n8.x4.shared.b16 {%0,%1,%2,%3}, [%4];" \
        : "=r"((r)[0]), "=r"((r)[1]), "=r"((r)[2]), "=r"((r)[3]) : "r"(a))
#define LDSM2(r, a) \
    asm volatile("ldmatrix.sync.aligned.m8n8.x2.shared.b16 {%0,%1}, [%2];" \
        : "=r"((r)[0]), "=r"((r)[1]) : "r"(a))

#define MMA_F32(d, a, b) \
    asm volatile("mma.sync.aligned.m16n8k16.row.col.f32.f16.f16.f32 " \
        "{%0,%1,%2,%3}, {%4,%5,%6,%7}, {%8,%9}, {%0,%1,%2,%3};" \
        : "+f"((d)[0]), "+f"((d)[1]), "+f"((d)[2]), "+f"((d)[3]) \
        : "r"((a)[0]), "r"((a)[1]), "r"((a)[2]), "r"((a)[3]), "r"((b)[0]), "r"((b)[1]))

#define STS64(addr, v0, v1) \
    asm volatile("st.shared.v2.b32 [%0], {%1, %2};" :: "r"(addr), "r"(v0), "r"(v1))

// ---------------- prepass: W1 cvt + counter reset ----------------
__global__ void cvt_w1(const float* __restrict__ W1) {
    __shared__ float t[32][33];
    int n0 = blockIdx.x * 32, k0 = blockIdx.y * 32;
    int tx = threadIdx.x, ty = threadIdx.y;
    int tid = ty * 32 + tx;
    if (blockIdx.x == 0 && blockIdx.y == 0)
        g_cnt[tid] = 0;                        // reset all 256 counters each replay
    #pragma unroll
    for (int i = 0; i < 4; i++)
        t[ty + i * 8][tx] = W1[(size_t)(k0 + ty + i * 8) * H_ + n0 + tx];
    __syncthreads();
    #pragma unroll
    for (int i = 0; i < 4; i++) {
        int n = ty + i * 8, k = tx;
        g_w1t[(size_t)(n0 + n) * D_ + k0 + k] = __float2half_rn(t[k][n]);
    }
}

// ---------------- GEMM1: relu(x@W1+b1), chunk column-sum, last-CTA logits ----------------
__global__ __launch_bounds__(NTHR_, 2)
void gemm1_mma(const float* __restrict__ x, const float* __restrict__ b1,
               const float* __restrict__ W2, const float* __restrict__ b2) {
    extern __shared__ __align__(1024) char smem[];
    const uint32_t sb = smem_to_u32(smem);
    const int tid = threadIdx.x;
    const int lane = tid & 31, wid = tid >> 5;      // 8 warps
    const int wm = wid & 1, wn = wid >> 1;          // 2(m) x 4(n), warp tile 64x32
    const int n0 = blockIdx.x * BN_;
    const int chunk = blockIdx.y;
    const int m0 = chunk * BM_;

    if (tid < BN_) ((float*)(smem + SM_B1_))[tid] = b1[n0 + tid];

    // ---- A (x fp32, LDG prefetch): thread covers 4 float4 chunks ----
    const int a_row0 = tid >> 3;            // +32*j
    const int a_k4   = tid & 7;
    const float* srcA0 = x + (size_t)(m0 + a_row0) * D_ + a_k4 * 4;
    const uint32_t dstA0 = sb + a_row0 * ROWB_ + a_k4 * 8;   // fp16: 8B per float4

    // ---- B (w1t fp16, cp.async): 2 chunks of 16B per thread ----
    const char* srcB[2]; uint32_t dstB[2];
    #pragma unroll
    for (int j = 0; j < 2; j++) {
        int q = tid + j * NTHR_;               // 0..511
        int row = q >> 2, k16 = q & 3;
        srcB[j] = (const char*)(g_w1t + (size_t)(n0 + row) * D_ + k16 * 8);
        dstB[j] = sb + ATILE_ + row * ROWB_ + k16 * 16;
    }

    const uint32_t a_off = (uint32_t)((wm * 64 + (lane & 15)) * ROWB_ + (lane >> 4) * 16);
    const uint32_t b_off = (uint32_t)(ATILE_ + (wn * 32 + (lane & 7)) * ROWB_ + ((lane >> 3) & 1) * 16);

    float acc[4][4][4];
    #pragma unroll
    for (int a = 0; a < 4; a++)
        #pragma unroll
        for (int b = 0; b < 4; b++)
            #pragma unroll
            for (int c = 0; c < 4; c++) acc[a][b][c] = 0.f;

    float4 areg[4];

    // ---- prologue ----
    #pragma unroll
    for (int j = 0; j < 4; j++)
        areg[j] = *(const float4*)(srcA0 + (size_t)(32 * j) * D_);
    #pragma unroll
    for (int j = 0; j < 4; j++) {
        uint32_t h0 = pack_half2(areg[j].x, areg[j].y);
        uint32_t h1 = pack_half2(areg[j].z, areg[j].w);
        STS64(dstA0 + j * (32 * ROWB_), h0, h1);
    }
    #pragma unroll
    for (int j = 0; j < 4; j++)
        areg[j] = *(const float4*)(srcA0 + (size_t)(32 * j) * D_ + BK_);
    #pragma unroll
    for (int s = 0; s < 2; s++) {
        uint32_t sbase = s * STAGE_SZ_;
        #pragma unroll
        for (int j = 0; j < 2; j++)
            CP_ASYNC16(dstB[j] + sbase, srcB[j] + s * 64);
        CP_COMMIT();
    }

    int buf = 0;
    for (int ck = 0; ck < NKC_; ck++) {
        CP_WAIT1();
        __syncthreads();

        if (ck + 1 < NKC_) {
            int nb1 = buf + 1; if (nb1 >= 3) nb1 -= 3;
            uint32_t ab = dstA0 + nb1 * STAGE_SZ_;
            #pragma unroll
            for (int j = 0; j < 4; j++) {
                uint32_t h0 = pack_half2(areg[j].x, areg[j].y);
                uint32_t h1 = pack_half2(areg[j].z, areg[j].w);
                STS64(ab + j * (32 * ROWB_), h0, h1);
            }
        }
        if (ck + 2 < NKC_) {
            #pragma unroll
            for (int j = 0; j < 4; j++)
                areg[j] = *(const float4*)(srcA0 + (size_t)(32 * j) * D_ + (size_t)(ck + 2) * BK_);
            int nb2 = buf + 2; if (nb2 >= 3) nb2 -= 3;
            uint32_t sbase = nb2 * STAGE_SZ_;
            #pragma unroll
            for (int j = 0; j < 2; j++)
                CP_ASYNC16(dstB[j] + sbase, srcB[j] + (size_t)(ck + 2) * 64);
        }
        CP_COMMIT();

        const uint32_t bufbase = sb + buf * STAGE_SZ_;
        #pragma unroll
        for (int kk = 0; kk < 2; kk++) {
            uint32_t ah[4][4], bh[4][2];
            uint32_t ab = bufbase + a_off + kk * 32;
            uint32_t bb = bufbase + b_off + kk * 32;
            #pragma unroll
            for (int mt = 0; mt < 4; mt++) LDSM4(ah[mt], ab + mt * (16 * ROWB_));
            #pragma unroll
            for (int nt = 0; nt < 4; nt++) LDSM2(bh[nt], bb + nt * (8 * ROWB_));
            #pragma unroll
            for (int mt = 0; mt < 4; mt++)
                #pragma unroll
                for (int nt = 0; nt < 4; nt++)
                    MMA_F32(acc[mt][nt], ah[mt], bh[nt]);
        }
        buf++; if (buf >= 3) buf = 0;
    }

    // ---- epilogue: relu(acc + b1), chunk column-sums ----
    const float* sb1f = (const float*)(smem + SM_B1_);
    float csum[4][2];
    #pragma unroll
    for (int nt = 0; nt < 4; nt++) { csum[nt][0] = 0.f; csum[nt][1] = 0.f; }
    #pragma unroll
    for (int nt = 0; nt < 4; nt++) {
        int col = wn * 32 + nt * 8 + (lane & 3) * 2;
        float bv0 = sb1f[col], bv1 = sb1f[col + 1];
        #pragma unroll
        for (int mt = 0; mt < 4; mt++) {
            csum[nt][0] += fmaxf(acc[mt][nt][0] + bv0, 0.f) + fmaxf(acc[mt][nt][2] + bv0, 0.f);
            csum[nt][1] += fmaxf(acc[mt][nt][1] + bv1, 0.f) + fmaxf(acc[mt][nt][3] + bv1, 0.f);
        }
    }
    #pragma unroll
    for (int nt = 0; nt < 4; nt++)
        #pragma unroll
        for (int r = 0; r < 2; r++) {
            csum[nt][r] += __shfl_xor_sync(0xffffffffu, csum[nt][r], 4);
            csum[nt][r] += __shfl_xor_sync(0xffffffffu, csum[nt][r], 8);
            csum[nt][r] += __shfl_xor_sync(0xffffffffu, csum[nt][r], 16);
        }
    float* part = (float*)(smem + SM_PART_);    // [2][128]
    __syncthreads();
    if (lane < 4) {
        #pragma unroll
        for (int nt = 0; nt < 4; nt++) {
            int col = wn * 32 + nt * 8 + lane * 2;
            part[wm * BN_ + col] = csum[nt][0];
            part[wm * BN_ + col + 1] = csum[nt][1];
        }
    }
    __syncthreads();
    if (tid < BN_)
        g_hsum[(size_t)chunk * H_ + n0 + tid] = part[tid] + part[BN_ + tid];

    // ---- last-CTA-per-chunk: compute this chunk's 8 logits ----
    __threadfence();
    __shared__ int slast;
    if (tid == 0) slast = (atomicAdd(&g_cnt[chunk], 1) == 7) ? 1 : 0;
    __syncthreads();
    if (slast) {
        const float* hs = g_hsum + (size_t)chunk * H_;
        float lacc[E_];
        #pragma unroll
        for (int e = 0; e < E_; e++) lacc[e] = 0.f;
        for (int j = tid; j < H_; j += NTHR_) {
            float h = hs[j];
            float4 w0 = *(const float4*)(W2 + (size_t)j * E_);
            float4 w1 = *(const float4*)(W2 + (size_t)j * E_ + 4);
            lacc[0] += h * w0.x; lacc[1] += h * w0.y; lacc[2] += h * w0.z; lacc[3] += h * w0.w;
            lacc[4] += h * w1.x; lacc[5] += h * w1.y; lacc[6] += h * w1.z; lacc[7] += h * w1.w;
        }
        #pragma unroll
        for (int off = 16; off; off >>= 1)
            #pragma unroll
            for (int e = 0; e < E_; e++)
                lacc[e] += __shfl_down_sync(0xffffffffu, lacc[e], off);
        float* sred = part;                       // reuse [8][8]
        if (lane == 0) {
            #pragma unroll
            for (int e = 0; e < E_; e++) sred[wid * E_ + e] = lacc[e];
        }
        __syncthreads();
        if (tid < E_) {
            float s = 0.f;
            #pragma unroll
            for (int g = 0; g < 8; g++) s += sred[g * E_ + tid];
            g_clogits[chunk * E_ + tid] = s * (1.0f / (float)CHUNK_) + b2[tid];
        }
    }
}

// ---------------- per-chunk scan + one-hot fill (256 blocks, one per chunk) ----------------
__global__ __launch_bounds__(256)
void scan_fill(float* __restrict__ out, int out_size) {
    __shared__ float clog[32 * E_];     // this batch's chunk logits
    __shared__ int   sidx;
    const int bc = blockIdx.x;          // global chunk 0..255
    const int b = bc >> 5, c = bc & 31;
    const int tid = threadIdx.x;

    clog[tid] = g_clogits[b * 32 * E_ + tid];   // 256 floats, coalesced
    __syncthreads();

    if (tid == 0) {
        int prev = 0;
        {
            float best = clog[0];
            #pragma unroll
            for (int e = 1; e < E_; e++)
                if (clog[e] > best) { best = clog[e]; prev = e; }
        }
        for (int cc = 1; cc <= c; cc++) {
            const float* l = clog + cc * E_;
            int ce = 0; float best = l[0];
            #pragma unroll
            for (int e = 1; e < E_; e++)
                if (l[e] > best) { best = l[e]; ce = e; }
            if (l[ce] - l[prev] > TAU_) prev = ce;
        }
        sidx = prev;
        if (out_size >= B_ * S_ * E_ + NCHUNK_)
            out[B_ * S_ * E_ + bc] = (float)prev;
    }
    __syncthreads();

    // one-hot fill for this chunk: 128 tokens x 8 = 256 float4
    const int idx = sidx;
    float4* ob = (float4*)out + (size_t)bc * 256;
    int e0 = (tid & 1) * 4;
    float4 v;
    v.x = (e0 + 0 == idx) ? 1.0f : 0.0f;
    v.y = (e0 + 1 == idx) ? 1.0f : 0.0f;
    v.z = (e0 + 2 == idx) ? 1.0f : 0.0f;
    v.w = (e0 + 3 == idx) ? 1.0f : 0.0f;
    ob[tid] = v;
}

extern "C" void kernel_launch(void* const* d_in, const int* in_sizes, int n_in,
                              void* d_out, int out_size) {
    const float* x  = (const float*)d_in[0];
    const float* W1 = (const float*)d_in[1];
    const float* b1 = (const float*)d_in[2];
    const float* W2 = (const float*)d_in[3];
    const float* b2 = (const float*)d_in[4];
    float* out = (float*)d_out;

    cudaFuncSetAttribute(gemm1_mma, cudaFuncAttributeMaxDynamicSharedMemorySize, SMEM_TOTAL_);

    cvt_w1<<<dim3(H_ / 32, D_ / 32), dim3(32, 8)>>>(W1);
    gemm1_mma<<<dim3(H_ / BN_, NCHUNK_), NTHR_, SMEM_TOTAL_>>>(x, b1, W2, b2);
    scan_fill<<<NCHUNK_, 256>>>(out, out_size);
}

// round 14
// speedup vs baseline: 1.1385x; 1.0363x over previous
#include <cuda_runtime.h>
#include <cuda_fp16.h>
#include <cstdint>

// ChunkStickyRouter on GB300 (sm_103a) — fp16 mma.sync GEMM1, 4+5-stage pipeline
// with barrier every 2nd k-chunk, fused x-cvt, last-CTA logits, per-chunk scan+fill.
// B=8, S=4096, D=2048, H=1024, E=8, CHUNK=128, TAU=0.7

#define B_  8
#define S_  4096
#define D_  2048
#define H_  1024
#define E_  8
#define CHUNK_ 128
#define NCHUNK_ 256
#define TAU_ 0.7f

// GEMM1 tiling
#define BM_ 128
#define BN_ 128
#define BK_ 32
#define NKC_ (D_ / BK_)        // 64
#define NTHR_ 256
#define ROWB_ 80               // smem row stride (bytes): conflict-free LDSM
#define TILE_ (128 * ROWB_)            // 10240 B per fp16 tile
#define NA_ 4                          // A stages
#define NB_ 5                          // B stages
#define BOFF_ (NA_ * TILE_)            // 40960
#define SM_B1_   (BOFF_ + NB_ * TILE_) // 92160
#define SM_PART_ (SM_B1_ + 512)
#define SMEM_TOTAL_ (SM_PART_ + 1024)  // 93696  -> 2 CTAs/SM

__device__ __half g_w1t[(size_t)H_ * D_];         // W1^T as fp16, [n][k]
__device__ float  g_hsum[NCHUNK_ * H_];
__device__ float  g_clogits[NCHUNK_ * E_];
__device__ int    g_cnt[NCHUNK_];                 // per-chunk completion counters

// ---------------- PTX helpers ----------------
__device__ __forceinline__ uint32_t smem_to_u32(const void* p) {
    uint32_t a;
    asm("{ .reg .u64 t; cvta.to.shared.u64 t, %1; cvt.u32.u64 %0, t; }" : "=r"(a) : "l"(p));
    return a;
}
__device__ __forceinline__ uint32_t pack_half2(float x, float y) {
    uint32_t u;
    asm("cvt.rn.f16x2.f32 %0, %1, %2;" : "=r"(u) : "f"(y), "f"(x));
    return u;
}
#define CP_ASYNC16(dst, src) \
    asm volatile("cp.async.cg.shared.global [%0], [%1], 16;" :: "r"(dst), "l"(src))
#define CP_COMMIT() asm volatile("cp.async.commit_group;" ::: "memory")
#define CP_WAITG1() asm volatile("cp.async.wait_group 1;" ::: "memory")

#define LDSM4(r, a) \
    asm volatile("ldmatrix.sync.aligned.m8n8.x4.shared.b16 {%0,%1,%2,%3}, [%4];" \
        : "=r"((r)[0]), "=r"((r)[1]), "=r"((r)[2]), "=r"((r)[3]) : "r"(a))
#define LDSM2(r, a) \
    asm volatile("ldmatrix.sync.aligned.m8n8.x2.shared.b16 {%0,%1}, [%2];" \
        : "=r"((r)[0]), "=r"((r)[1]) : "r"(a))

#define MMA_F32(d, a, b) \
    asm volatile("mma.sync.aligned.m16n8k16.row.col.f32.f16.f16.f32 " \
        "{%0,%1,%2,%3}, {%4,%5,%6,%7}, {%8,%9}, {%0,%1,%2,%3};" \
        : "+f"((d)[0]), "+f"((d)[1]), "+f"((d)[2]), "+f"((d)[3]) \
        : "r"((a)[0]), "r"((a)[1]), "r"((a)[2]), "r"((a)[3]), "r"((b)[0]), "r"((b)[1]))

#define STS64(addr, v0, v1) \
    asm volatile("st.shared.v2.b32 [%0], {%1, %2};" :: "r"(addr), "r"(v0), "r"(v1))

// ---------------- prepass: W1 cvt (vectorized stores) + counter reset ----------------
__global__ void cvt_w1(const float* __restrict__ W1) {
    __shared__ float t[32][33];
    int n0 = blockIdx.x * 32, k0 = blockIdx.y * 32;
    int tx = threadIdx.x, ty = threadIdx.y;
    int tid = ty * 32 + tx;
    if (blockIdx.x == 0 && blockIdx.y == 0)
        g_cnt[tid] = 0;
    #pragma unroll
    for (int i = 0; i < 4; i++)
        t[ty + i * 8][tx] = W1[(size_t)(k0 + ty + i * 8) * H_ + n0 + tx];
    __syncthreads();
    // thread -> (n, 4 consecutive k); 8B store
    int n = tid >> 3, k4 = (tid & 7) * 4;
    uint2 h;
    h.x = pack_half2(t[k4 + 0][n], t[k4 + 1][n]);
    h.y = pack_half2(t[k4 + 2][n], t[k4 + 3][n]);
    *(uint2*)&g_w1t[(size_t)(n0 + n) * D_ + k0 + k4] = h;
}

// ---------------- GEMM1: relu(x@W1+b1), chunk column-sum, last-CTA logits ----------------
__global__ __launch_bounds__(NTHR_, 2)
void gemm1_mma(const float* __restrict__ x, const float* __restrict__ b1,
               const float* __restrict__ W2, const float* __restrict__ b2) {
    extern __shared__ __align__(1024) char smem[];
    const uint32_t sb = smem_to_u32(smem);
    const int tid = threadIdx.x;
    const int lane = tid & 31, wid = tid >> 5;      // 8 warps
    const int wm = wid & 1, wn = wid >> 1;          // 2(m) x 4(n), warp tile 64x32
    const int n0 = blockIdx.x * BN_;
    const int chunk = blockIdx.y;
    const int m0 = chunk * BM_;

    if (tid < BN_) ((float*)(smem + SM_B1_))[tid] = b1[n0 + tid];

    // ---- A (x fp32, LDG prefetch): thread covers 4 float4 chunks ----
    const int a_row0 = tid >> 3;            // +32*j
    const int a_k4   = tid & 7;
    const float* srcA0 = x + (size_t)(m0 + a_row0) * D_ + a_k4 * 4;
    const uint32_t dstA0 = sb + a_row0 * ROWB_ + a_k4 * 8;   // fp16: 8B per float4

    // ---- B (w1t fp16, cp.async): 2 chunks of 16B per thread ----
    const char* srcB[2]; uint32_t dstB[2];
    #pragma unroll
    for (int j = 0; j < 2; j++) {
        int q = tid + j * NTHR_;               // 0..511
        int row = q >> 2, k16 = q & 3;
        srcB[j] = (const char*)(g_w1t + (size_t)(n0 + row) * D_ + k16 * 8);
        dstB[j] = sb + BOFF_ + row * ROWB_ + k16 * 16;
    }

    const uint32_t a_off = (uint32_t)((wm * 64 + (lane & 15)) * ROWB_ + (lane >> 4) * 16);
    const uint32_t b_off = (uint32_t)(BOFF_ + (wn * 32 + (lane & 7)) * ROWB_ + ((lane >> 3) & 1) * 16);

    float acc[4][4][4];
    #pragma unroll
    for (int a = 0; a < 4; a++)
        #pragma unroll
        for (int b = 0; b < 4; b++)
            #pragma unroll
            for (int c = 0; c < 4; c++) acc[a][b][c] = 0.f;

    float4 areg[4];

    // ---- prologue: A0,A1 -> smem; A2 -> regs; B0,B1,B2 cp.async ----
    #pragma unroll
    for (int s = 0; s < 2; s++) {
        #pragma unroll
        for (int j = 0; j < 4; j++)
            areg[j] = *(const float4*)(srcA0 + (size_t)(32 * j) * D_ + s * BK_);
        #pragma unroll
        for (int j = 0; j < 4; j++) {
            uint32_t h0 = pack_half2(areg[j].x, areg[j].y);
            uint32_t h1 = pack_half2(areg[j].z, areg[j].w);
            STS64(dstA0 + s * TILE_ + j * (32 * ROWB_), h0, h1);
        }
    }
    #pragma unroll
    for (int j = 0; j < 4; j++)
        areg[j] = *(const float4*)(srcA0 + (size_t)(32 * j) * D_ + 2 * BK_);
    #pragma unroll
    for (int s = 0; s < 3; s++) {
        #pragma unroll
        for (int j = 0; j < 2; j++)
            CP_ASYNC16(dstB[j] + s * TILE_, srcB[j] + s * 64);
        CP_COMMIT();
    }

    int bufA = 0, bufB = 0;                 // ck % 4, ck % 5
    for (int ck = 0; ck < NKC_; ck++) {
        if ((ck & 1) == 0) {
            CP_WAITG1();
            __syncthreads();
        }

        // stage A(ck+2) regs -> bufA[(ck+2)%4] ; prefetch A(ck+3)
        if (ck + 2 < NKC_) {
            int nb = bufA + 2; if (nb >= NA_) nb -= NA_;
            uint32_t ab = dstA0 + nb * TILE_;
            #pragma unroll
            for (int j = 0; j < 4; j++) {
                uint32_t h0 = pack_half2(areg[j].x, areg[j].y);
                uint32_t h1 = pack_half2(areg[j].z, areg[j].w);
                STS64(ab + j * (32 * ROWB_), h0, h1);
            }
        }
        if (ck + 3 < NKC_) {
            #pragma unroll
            for (int j = 0; j < 4; j++)
                areg[j] = *(const float4*)(srcA0 + (size_t)(32 * j) * D_ + (size_t)(ck + 3) * BK_);
            // B(ck+3) -> bufB[(ck+3)%5]
            int nb = bufB + 3; if (nb >= NB_) nb -= NB_;
            uint32_t sbase = nb * TILE_;
            #pragma unroll
            for (int j = 0; j < 2; j++)
                CP_ASYNC16(dstB[j] + sbase, srcB[j] + (size_t)(ck + 3) * 64);
        }
        CP_COMMIT();   // unconditional: keeps group counting uniform

        const uint32_t abase = sb + bufA * TILE_;
        const uint32_t bbase = sb + bufB * TILE_;   // b_off already includes BOFF_
        #pragma unroll
        for (int kk = 0; kk < 2; kk++) {
            uint32_t ah[4][4], bh[4][2];
            uint32_t ab = abase + a_off + kk * 32;
            uint32_t bb = bbase + b_off + kk * 32;
            #pragma unroll
            for (int mt = 0; mt < 4; mt++) LDSM4(ah[mt], ab + mt * (16 * ROWB_));
            #pragma unroll
            for (int nt = 0; nt < 4; nt++) LDSM2(bh[nt], bb + nt * (8 * ROWB_));
            #pragma unroll
            for (int mt = 0; mt < 4; mt++)
                #pragma unroll
                for (int nt = 0; nt < 4; nt++)
                    MMA_F32(acc[mt][nt], ah[mt], bh[nt]);
        }
        bufA++; if (bufA >= NA_) bufA = 0;
        bufB++; if (bufB >= NB_) bufB = 0;
    }

    // ---- epilogue: relu(acc + b1), chunk column-sums ----
    const float* sb1f = (const float*)(smem + SM_B1_);
    float csum[4][2];
    #pragma unroll
    for (int nt = 0; nt < 4; nt++) { csum[nt][0] = 0.f; csum[nt][1] = 0.f; }
    #pragma unroll
    for (int nt = 0; nt < 4; nt++) {
        int col = wn * 32 + nt * 8 + (lane & 3) * 2;
        float bv0 = sb1f[col], bv1 = sb1f[col + 1];
        #pragma unroll
        for (int mt = 0; mt < 4; mt++) {
            csum[nt][0] += fmaxf(acc[mt][nt][0] + bv0, 0.f) + fmaxf(acc[mt][nt][2] + bv0, 0.f);
            csum[nt][1] += fmaxf(acc[mt][nt][1] + bv1, 0.f) + fmaxf(acc[mt][nt][3] + bv1, 0.f);
        }
    }
    #pragma unroll
    for (int nt = 0; nt < 4; nt++)
        #pragma unroll
        for (int r = 0; r < 2; r++) {
            csum[nt][r] += __shfl_xor_sync(0xffffffffu, csum[nt][r], 4);
            csum[nt][r] += __shfl_xor_sync(0xffffffffu, csum[nt][r], 8);
            csum[nt][r] += __shfl_xor_sync(0xffffffffu, csum[nt][r], 16);
        }
    float* part = (float*)(smem + SM_PART_);    // [2][128]
    __syncthreads();
    if (lane < 4) {
        #pragma unroll
        for (int nt = 0; nt < 4; nt++) {
            int col = wn * 32 + nt * 8 + lane * 2;
            part[wm * BN_ + col] = csum[nt][0];
            part[wm * BN_ + col + 1] = csum[nt][1];
        }
    }
    __syncthreads();
    if (tid < BN_)
        g_hsum[(size_t)chunk * H_ + n0 + tid] = part[tid] + part[BN_ + tid];

    // ---- last-CTA-per-chunk: compute this chunk's 8 logits ----
    __threadfence();
    __shared__ int slast;
    if (tid == 0) slast = (atomicAdd(&g_cnt[chunk], 1) == 7) ? 1 : 0;
    __syncthreads();
    if (slast) {
        const float* hs = g_hsum + (size_t)chunk * H_;
        float lacc[E_];
        #pragma unroll
        for (int e = 0; e < E_; e++) lacc[e] = 0.f;
        for (int j = tid; j < H_; j += NTHR_) {
            float h = hs[j];
            float4 w0 = *(const float4*)(W2 + (size_t)j * E_);
            float4 w1 = *(const float4*)(W2 + (size_t)j * E_ + 4);
            lacc[0] += h * w0.x; lacc[1] += h * w0.y; lacc[2] += h * w0.z; lacc[3] += h * w0.w;
            lacc[4] += h * w1.x; lacc[5] += h * w1.y; lacc[6] += h * w1.z; lacc[7] += h * w1.w;
        }
        #pragma unroll
        for (int off = 16; off; off >>= 1)
            #pragma unroll
            for (int e = 0; e < E_; e++)
                lacc[e] += __shfl_down_sync(0xffffffffu, lacc[e], off);
        float* sred = part;                       // reuse [8][8]
        if (lane == 0) {
            #pragma unroll
            for (int e = 0; e < E_; e++) sred[wid * E_ + e] = lacc[e];
        }
        __syncthreads();
        if (tid < E_) {
            float s = 0.f;
            #pragma unroll
            for (int g = 0; g < 8; g++) s += sred[g * E_ + tid];
            g_clogits[chunk * E_ + tid] = s * (1.0f / (float)CHUNK_) + b2[tid];
        }
    }
}

// ---------------- per-chunk scan + one-hot fill (256 blocks, one per chunk) ----------------
__global__ __launch_bounds__(256)
void scan_fill(float* __restrict__ out, int out_size) {
    __shared__ float clog[32 * E_];
    __shared__ int   sidx;
    const int bc = blockIdx.x;          // global chunk 0..255
    const int b = bc >> 5, c = bc & 31;
    const int tid = threadIdx.x;

    clog[tid] = g_clogits[b * 32 * E_ + tid];
    __syncthreads();

    if (tid == 0) {
        int prev = 0;
        {
            float best = clog[0];
            #pragma unroll
            for (int e = 1; e < E_; e++)
                if (clog[e] > best) { best = clog[e]; prev = e; }
        }
        for (int cc = 1; cc <= c; cc++) {
            const float* l = clog + cc * E_;
            int ce = 0; float best = l[0];
            #pragma unroll
            for (int e = 1; e < E_; e++)
                if (l[e] > best) { best = l[e]; ce = e; }
            if (l[ce] - l[prev] > TAU_) prev = ce;
        }
        sidx = prev;
        if (out_size >= B_ * S_ * E_ + NCHUNK_)
            out[B_ * S_ * E_ + bc] = (float)prev;
    }
    __syncthreads();

    const int idx = sidx;
    float4* ob = (float4*)out + (size_t)bc * 256;
    int e0 = (tid & 1) * 4;
    float4 v;
    v.x = (e0 + 0 == idx) ? 1.0f : 0.0f;
    v.y = (e0 + 1 == idx) ? 1.0f : 0.0f;
    v.z = (e0 + 2 == idx) ? 1.0f : 0.0f;
    v.w = (e0 + 3 == idx) ? 1.0f : 0.0f;
    ob[tid] = v;
}

extern "C" void kernel_launch(void* const* d_in, const int* in_sizes, int n_in,
                              void* d_out, int out_size) {
    const float* x  = (const float*)d_in[0];
    const float* W1 = (const float*)d_in[1];
    const float* b1 = (const float*)d_in[2];
    const float* W2 = (const float*)d_in[3];
    const float* b2 = (const float*)d_in[4];
    float* out = (float*)d_out;

    cudaFuncSetAttribute(gemm1_mma, cudaFuncAttributeMaxDynamicSharedMemorySize, SMEM_TOTAL_);

    cvt_w1<<<dim3(H_ / 32, D_ / 32), dim3(32, 8)>>>(W1);
    gemm1_mma<<<dim3(H_ / BN_, NCHUNK_), NTHR_, SMEM_TOTAL_>>>(x, b1, W2, b2);
    scan_fill<<<NCHUNK_, 256>>>(out, out_size);
}